// round 12
// baseline (speedup 1.0000x reference)
#include <cuda_runtime.h>
#include <cuda_bf16.h>
#include <cstdint>

// Problem constants
#define BB    4
#define SS    4096
#define DD    1024
#define MM    (BB * SS)      // 16384
#define NN    (2 * DD)       // 2048
#define KK    DD             // 1024

#define NCHUNK 256
#define CLEN   (SS / NCHUNK) // 16
#define NCH    (BB * DD)     // 4096 channels

// Scratch (static device globals)
// g_cv holds interleaved (c,v) pairs: row m, cols [2d, 2d+1] = (c_d, v_d).
__device__ float g_cv[(size_t)MM * NN];          // 128 MiB
__device__ float g_chunkC[NCHUNK * NCH];
__device__ float g_chunkV[NCHUNK * NCH];
__device__ float g_h0[NCHUNK * NCH];
__device__ __align__(16) __nv_bfloat16 g_Ahi[(size_t)MM * KK];  // 32 MiB
__device__ __align__(16) __nv_bfloat16 g_Alo[(size_t)MM * KK];
__device__ __align__(16) __nv_bfloat16 g_Bhi[(size_t)NN * KK];  // 4 MiB (row-permuted W)
__device__ __align__(16) __nv_bfloat16 g_Blo[(size_t)NN * KK];

// ===========================================================================
// bf16 split helpers
// ===========================================================================
__device__ __forceinline__ uint32_t f2bf_bits(float x) {
    uint32_t u = __float_as_uint(x);
    return (u + 0x7FFFu + ((u >> 16) & 1u)) >> 16;
}
__device__ __forceinline__ float bf2f(uint32_t b) {
    return __uint_as_float(b << 16);
}
__device__ __forceinline__ void split4(float4 v, uint2& hi, uint2& lo) {
    uint32_t h0 = f2bf_bits(v.x), h1 = f2bf_bits(v.y);
    uint32_t h2 = f2bf_bits(v.z), h3 = f2bf_bits(v.w);
    float l0 = v.x - bf2f(h0), l1 = v.y - bf2f(h1);
    float l2 = v.z - bf2f(h2), l3 = v.w - bf2f(h3);
    uint32_t a0 = f2bf_bits(l0), a1 = f2bf_bits(l1);
    uint32_t a2 = f2bf_bits(l2), a3 = f2bf_bits(l3);
    hi = make_uint2(h0 | (h1 << 16), h2 | (h3 << 16));
    lo = make_uint2(a0 | (a1 << 16), a2 | (a3 << 16));
}

// ===========================================================================
// Convert: x -> (Ahi, Alo); W -> row-permuted (Bhi, Blo).
// Permutation: W row e -> 2e (hidden ch e) ; row e>=1024 -> 2(e-1024)+1 (gate).
// 8 floats per thread; one STG.128 per destination array.
// ===========================================================================
#define A8 ((size_t)MM * KK / 8)   // 2097152
#define B8 ((size_t)NN * KK / 8)   // 262144

__global__ __launch_bounds__(256)
void convert_kernel(const float* __restrict__ x, const float* __restrict__ W)
{
    const size_t i = (size_t)blockIdx.x * 256 + threadIdx.x;
    if (i < A8) {
        const float4 v0 = ((const float4*)x)[i * 2];
        const float4 v1 = ((const float4*)x)[i * 2 + 1];
        uint2 h0, l0, h1, l1;
        split4(v0, h0, l0);
        split4(v1, h1, l1);
        ((uint4*)g_Ahi)[i] = make_uint4(h0.x, h0.y, h1.x, h1.y);
        ((uint4*)g_Alo)[i] = make_uint4(l0.x, l0.y, l1.x, l1.y);
    } else if (i < A8 + B8) {
        const size_t j = i - A8;             // 8-float unit within W
        const size_t el = j * 8;
        const int e = (int)(el >> 10);       // source row
        const int col = (int)(el & 1023);
        const int p = (e < DD) ? (2 * e) : (2 * (e - DD) + 1);
        const float4 v0 = ((const float4*)W)[j * 2];
        const float4 v1 = ((const float4*)W)[j * 2 + 1];
        uint2 h0, l0, h1, l1;
        split4(v0, h0, l0);
        split4(v1, h1, l1);
        const size_t dst = ((size_t)p * KK + col) / 8;
        ((uint4*)g_Bhi)[dst] = make_uint4(h0.x, h0.y, h1.x, h1.y);
        ((uint4*)g_Blo)[dst] = make_uint4(l0.x, l0.y, l1.x, l1.y);
    }
}

// ===========================================================================
// c = sigmoid(-gate), v = sigmoid(gate)*g(hidden)
// ===========================================================================
__device__ __forceinline__ void compute_cv(float hidden, float gate,
                                           float& c, float& v)
{
    const float eg = __expf(gate);
    c = 1.f / (1.f + eg);
    const float z = 1.f - c;
    float gg;
    if (hidden >= 0.f) gg = hidden + 0.5f;
    else               gg = 1.f / (1.f + __expf(-hidden));
    v = z * gg;
}

// ===========================================================================
// GEMM: hg = [Ahi|Ahi|Alo] * [Bhi|Blo|Bhi]^T over virtual K = 3072 bf16.
// CTA 128x128, BK=64, 3-stage cp.async, ldmatrix, 8 warps, 2 CTAs/SM.
// Epilogue computes (c,v) from each (hidden,gate) accumulator pair.
// ===========================================================================
#define TM 128
#define TN 128
#define BKB 64
#define KCHUNKS 48                 // 3 segments x 16 chunks
#define AST 16384
#define STAGE_B 32768
#define GEMM_SMEM (3 * STAGE_B)    // 98304

#define CP_ASYNC16(dst, src) \
    asm volatile("cp.async.cg.shared.global [%0], [%1], 16;" \
                 :: "r"(dst), "l"(src))
#define CP_COMMIT() asm volatile("cp.async.commit_group;")
#define CP_WAIT1()  asm volatile("cp.async.wait_group 1;")
#define CP_WAIT0()  asm volatile("cp.async.wait_group 0;")
#define LDSM4(r0, r1, r2, r3, addr) \
    asm volatile("ldmatrix.sync.aligned.m8n8.x4.shared.b16 {%0,%1,%2,%3}, [%4];" \
                 : "=r"(r0), "=r"(r1), "=r"(r2), "=r"(r3) : "r"(addr))

__device__ __forceinline__ uint32_t smem_u32(const void* p) {
    uint32_t a;
    asm("{ .reg .u64 t; cvta.to.shared.u64 t, %1; cvt.u32.u64 %0, t; }"
        : "=r"(a) : "l"(p));
    return a;
}

__device__ __forceinline__ void mma_bf16(float& d0, float& d1, float& d2, float& d3,
                                         uint32_t a0, uint32_t a1, uint32_t a2, uint32_t a3,
                                         uint32_t b0, uint32_t b1)
{
    asm volatile(
        "mma.sync.aligned.m16n8k16.row.col.f32.bf16.bf16.f32 "
        "{%0,%1,%2,%3}, {%4,%5,%6,%7}, {%8,%9}, {%0,%1,%2,%3};"
        : "+f"(d0), "+f"(d1), "+f"(d2), "+f"(d3)
        : "r"(a0), "r"(a1), "r"(a2), "r"(a3), "r"(b0), "r"(b1));
}

struct ChunkSrc {
    const __nv_bfloat16* a;
    const __nv_bfloat16* b;
    int kk;
};
__device__ __forceinline__ ChunkSrc chunk_src(int kc) {
    ChunkSrc s;
    const int seg = kc >> 4;
    s.kk = (kc & 15) * BKB;
    s.a = (seg < 2) ? g_Ahi : g_Alo;
    s.b = (seg == 1) ? g_Blo : g_Bhi;
    return s;
}

__global__ __launch_bounds__(256, 2)
void mingru_gemm()
{
    extern __shared__ char smem[];
    const uint32_t sb = smem_u32(smem);
    const int tid = threadIdx.x;
    const int wid = tid >> 5, lid = tid & 31;
    const int m0 = blockIdx.y * TM, n0 = blockIdx.x * TN;

    const int crow0 = tid >> 3;
    const int cuc   = tid & 7;
    const uint32_t cdst0 = (uint32_t)(crow0 * 128 + ((cuc * 16) ^ ((crow0 & 7) << 4)));

    const int rr = lid & 7, q = lid >> 3;
    const int arow = (q & 1) * 8 + rr;
    const uint32_t acb = (uint32_t)((q >> 1) * 16);
    const int brow = (q >> 1) * 8 + rr;
    const uint32_t bcb = (uint32_t)((q & 1) * 16);
    const uint32_t lxr = (uint32_t)(rr << 4);

    const int wm = (wid >> 2) * 64;
    const int wn = (wid & 3) * 32;
    const int gg = lid >> 2;
    const int t4 = lid & 3;

    float acc[4][4][4];
#pragma unroll
    for (int i = 0; i < 4; i++)
#pragma unroll
        for (int j = 0; j < 4; j++)
#pragma unroll
            for (int e = 0; e < 4; e++) acc[i][j][e] = 0.f;

    auto issue = [&](int kc, int s) {
        const ChunkSrc cs = chunk_src(kc);
        const uint32_t As = sb + s * STAGE_B;
        const uint32_t Bs = As + AST;
#pragma unroll
        for (int i = 0; i < 4; i++) {
            const int row = crow0 + i * 32;
            const uint32_t d = cdst0 + i * 4096;
            CP_ASYNC16(As + d, cs.a + (size_t)(m0 + row) * KK + cs.kk + cuc * 8);
            CP_ASYNC16(Bs + d, cs.b + (size_t)(n0 + row) * KK + cs.kk + cuc * 8);
        }
        CP_COMMIT();
    };

    issue(0, 0);
    issue(1, 1);

    for (int kc = 0; kc < KCHUNKS; kc++) {
        if (kc == KCHUNKS - 1) { CP_WAIT0(); } else { CP_WAIT1(); }
        __syncthreads();

        if (kc + 2 < KCHUNKS) issue(kc + 2, (kc + 2) % 3);

        const uint32_t As = sb + (kc % 3) * STAGE_B;
        const uint32_t Bs = As + AST;

#pragma unroll
        for (int kt = 0; kt < 4; kt++) {
            uint32_t af[4][4];
#pragma unroll
            for (int i = 0; i < 4; i++) {
                const uint32_t addr = As + (uint32_t)((wm + i * 16 + arow) * 128)
                                    + (((uint32_t)(kt * 32) + acb) ^ lxr);
                LDSM4(af[i][0], af[i][1], af[i][2], af[i][3], addr);
            }
            uint32_t bf[4][2];
            {
                const uint32_t addr0 = Bs + (uint32_t)((wn + brow) * 128)
                                     + (((uint32_t)(kt * 32) + bcb) ^ lxr);
                LDSM4(bf[0][0], bf[0][1], bf[1][0], bf[1][1], addr0);
                LDSM4(bf[2][0], bf[2][1], bf[3][0], bf[3][1], addr0 + 16 * 128);
            }
#pragma unroll
            for (int i = 0; i < 4; i++)
#pragma unroll
                for (int j = 0; j < 4; j++)
                    mma_bf16(acc[i][j][0], acc[i][j][1], acc[i][j][2], acc[i][j][3],
                             af[i][0], af[i][1], af[i][2], af[i][3],
                             bf[j][0], bf[j][1]);
        }
    }

    // Epilogue: each acc float2 pair = (hidden_d, gate_d); store (c_d, v_d).
#pragma unroll
    for (int i = 0; i < 4; i++) {
        const int r0 = m0 + wm + i * 16 + gg;
#pragma unroll
        for (int j = 0; j < 4; j++) {
            const int c = n0 + wn + j * 8 + t4 * 2;   // even: pair (c, c+1)
            float cv0, vv0, cv1, vv1;
            compute_cv(acc[i][j][0], acc[i][j][1], cv0, vv0);
            compute_cv(acc[i][j][2], acc[i][j][3], cv1, vv1);
            *(float2*)(g_cv + (size_t)r0 * NN + c)       = make_float2(cv0, vv0);
            *(float2*)(g_cv + (size_t)(r0 + 8) * NN + c) = make_float2(cv1, vv1);
        }
    }
}

// ===========================================================================
// Scan passes (pure FMA streaming; (c,v) precomputed in GEMM epilogue).
// Thread t owns channels 4t..4t+3 = cols 8t..8t+7 of g_cv.
// ===========================================================================
__global__ __launch_bounds__(256)
void scan_passA()
{
    const int t = threadIdx.x;
    const int k = blockIdx.x;
    const int b = blockIdx.y;
    const size_t base = ((size_t)b * SS + (size_t)k * CLEN) * NN + t * 8;
    const float4* p0 = (const float4*)(g_cv + base);

    float C[4] = {1.f, 1.f, 1.f, 1.f};
    float V[4] = {0.f, 0.f, 0.f, 0.f};
#pragma unroll 8
    for (int s = 0; s < CLEN; s++) {
        const float4 a = p0[s * (NN / 4)];           // c0 v0 c1 v1
        const float4 bq = p0[s * (NN / 4) + 1];      // c2 v2 c3 v3
        V[0] = fmaf(a.x, V[0], a.y);   C[0] *= a.x;
        V[1] = fmaf(a.z, V[1], a.w);   C[1] *= a.z;
        V[2] = fmaf(bq.x, V[2], bq.y); C[2] *= bq.x;
        V[3] = fmaf(bq.z, V[3], bq.w); C[3] *= bq.z;
    }
    const int ch = b * DD + t * 4;
    *(float4*)&g_chunkC[k * NCH + ch] = make_float4(C[0], C[1], C[2], C[3]);
    *(float4*)&g_chunkV[k * NCH + ch] = make_float4(V[0], V[1], V[2], V[3]);
}

// Warp-per-channel associative scan over the 256 chunk transforms.
#define KPL (NCHUNK / 32)   // 8 chunks per lane
__global__ __launch_bounds__(256)
void scan_passB()
{
    const int warp = (blockIdx.x * 256 + threadIdx.x) >> 5;  // 0..4095 == ch
    const int lane = threadIdx.x & 31;
    const int ch = warp;

    float c8[KPL], v8[KPL];
#pragma unroll
    for (int j = 0; j < KPL; j++) {
        const int k = lane * KPL + j;
        c8[j] = g_chunkC[k * NCH + ch];
        v8[j] = g_chunkV[k * NCH + ch];
    }
    float C = c8[0], V = v8[0];
#pragma unroll
    for (int j = 1; j < KPL; j++) {
        V = fmaf(c8[j], V, v8[j]);
        C *= c8[j];
    }
#pragma unroll
    for (int off = 1; off < 32; off <<= 1) {
        const float Cp = __shfl_up_sync(0xFFFFFFFFu, C, off);
        const float Vp = __shfl_up_sync(0xFFFFFFFFu, V, off);
        if (lane >= off) {
            V = fmaf(C, Vp, V);
            C *= Cp;
        }
    }
    const float Vprev = __shfl_up_sync(0xFFFFFFFFu, V, 1);
    float h = (lane == 0) ? 0.f : Vprev;
#pragma unroll
    for (int j = 0; j < KPL; j++) {
        const int k = lane * KPL + j;
        g_h0[k * NCH + ch] = h;
        h = fmaf(c8[j], h, v8[j]);
    }
}

__global__ __launch_bounds__(256)
void scan_passC(float* __restrict__ out)
{
    const int t = threadIdx.x;
    const int k = blockIdx.x;
    const int b = blockIdx.y;
    const size_t base = ((size_t)b * SS + (size_t)k * CLEN) * NN + t * 8;
    const float4* p0 = (const float4*)(g_cv + base);

    const int ch = b * DD + t * 4;
    const float4 h0v = *(const float4*)&g_h0[k * NCH + ch];
    float h[4] = {h0v.x, h0v.y, h0v.z, h0v.w};

    float4* po = (float4*)(out + ((size_t)b * SS + (size_t)k * CLEN) * DD + t * 4);
#pragma unroll 8
    for (int s = 0; s < CLEN; s++) {
        const float4 a = p0[s * (NN / 4)];
        const float4 bq = p0[s * (NN / 4) + 1];
        h[0] = fmaf(a.x, h[0], a.y);
        h[1] = fmaf(a.z, h[1], a.w);
        h[2] = fmaf(bq.x, h[2], bq.y);
        h[3] = fmaf(bq.z, h[3], bq.w);
        po[s * (DD / 4)] = make_float4(h[0], h[1], h[2], h[3]);
    }
}

// ===========================================================================
extern "C" void kernel_launch(void* const* d_in, const int* in_sizes, int n_in,
                              void* d_out, int out_size)
{
    const float* x = (const float*)d_in[0];   // [B, S, D]
    const float* W = (const float*)d_in[1];   // [2D, D]
    float* out = (float*)d_out;

    cudaFuncSetAttribute(mingru_gemm,
                         cudaFuncAttributeMaxDynamicSharedMemorySize, GEMM_SMEM);

    convert_kernel<<<(unsigned)((A8 + B8 + 255) / 256), 256>>>(x, W);

    dim3 ggrid(NN / TN, MM / TM);            // (16, 128)
    mingru_gemm<<<ggrid, 256, GEMM_SMEM>>>();

    dim3 sgrid(NCHUNK, BB);                  // (256, 4)
    scan_passA<<<sgrid, 256>>>();
    scan_passB<<<(NCH * 32) / 256, 256>>>();
    scan_passC<<<sgrid, 256>>>(out);
}

// round 13
// speedup vs baseline: 1.0463x; 1.0463x over previous
#include <cuda_runtime.h>
#include <cuda_bf16.h>
#include <cstdint>

// Problem constants
#define BB    4
#define SS    4096
#define DD    1024
#define MM    (BB * SS)      // 16384
#define NN    (2 * DD)       // 2048
#define KK    DD             // 1024

#define NCHUNK 256
#define CLEN   (SS / NCHUNK) // 16
#define NCH    (BB * DD)     // 4096 channels

// Scratch (static device globals)
// g_cv holds interleaved (c,v) pairs: row m, cols [2d, 2d+1] = (c_d, v_d).
__device__ float g_cv[(size_t)MM * NN];          // 128 MiB
__device__ float g_chunkC[NCHUNK * NCH];
__device__ float g_chunkV[NCHUNK * NCH];
__device__ float g_h0[NCHUNK * NCH];
__device__ __align__(16) __nv_bfloat16 g_Ahi[(size_t)MM * KK];  // 32 MiB
__device__ __align__(16) __nv_bfloat16 g_Alo[(size_t)MM * KK];
__device__ __align__(16) __nv_bfloat16 g_Bhi[(size_t)NN * KK];  // 4 MiB (row-permuted W)
__device__ __align__(16) __nv_bfloat16 g_Blo[(size_t)NN * KK];

// ===========================================================================
// bf16 split helpers
// ===========================================================================
__device__ __forceinline__ uint32_t f2bf_bits(float x) {
    uint32_t u = __float_as_uint(x);
    return (u + 0x7FFFu + ((u >> 16) & 1u)) >> 16;
}
__device__ __forceinline__ float bf2f(uint32_t b) {
    return __uint_as_float(b << 16);
}
__device__ __forceinline__ void split4(float4 v, uint2& hi, uint2& lo) {
    uint32_t h0 = f2bf_bits(v.x), h1 = f2bf_bits(v.y);
    uint32_t h2 = f2bf_bits(v.z), h3 = f2bf_bits(v.w);
    float l0 = v.x - bf2f(h0), l1 = v.y - bf2f(h1);
    float l2 = v.z - bf2f(h2), l3 = v.w - bf2f(h3);
    uint32_t a0 = f2bf_bits(l0), a1 = f2bf_bits(l1);
    uint32_t a2 = f2bf_bits(l2), a3 = f2bf_bits(l3);
    hi = make_uint2(h0 | (h1 << 16), h2 | (h3 << 16));
    lo = make_uint2(a0 | (a1 << 16), a2 | (a3 << 16));
}

// ===========================================================================
// Convert: x -> (Ahi, Alo); W -> row-permuted (Bhi, Blo).
// Permutation: W row e -> 2e (hidden ch e) ; row e>=1024 -> 2(e-1024)+1 (gate).
// ===========================================================================
#define A8 ((size_t)MM * KK / 8)   // 2097152
#define B8 ((size_t)NN * KK / 8)   // 262144

__global__ __launch_bounds__(256)
void convert_kernel(const float* __restrict__ x, const float* __restrict__ W)
{
    const size_t i = (size_t)blockIdx.x * 256 + threadIdx.x;
    if (i < A8) {
        const float4 v0 = ((const float4*)x)[i * 2];
        const float4 v1 = ((const float4*)x)[i * 2 + 1];
        uint2 h0, l0, h1, l1;
        split4(v0, h0, l0);
        split4(v1, h1, l1);
        ((uint4*)g_Ahi)[i] = make_uint4(h0.x, h0.y, h1.x, h1.y);
        ((uint4*)g_Alo)[i] = make_uint4(l0.x, l0.y, l1.x, l1.y);
    } else if (i < A8 + B8) {
        const size_t j = i - A8;
        const size_t el = j * 8;
        const int e = (int)(el >> 10);
        const int col = (int)(el & 1023);
        const int p = (e < DD) ? (2 * e) : (2 * (e - DD) + 1);
        const float4 v0 = ((const float4*)W)[j * 2];
        const float4 v1 = ((const float4*)W)[j * 2 + 1];
        uint2 h0, l0, h1, l1;
        split4(v0, h0, l0);
        split4(v1, h1, l1);
        const size_t dst = ((size_t)p * KK + col) / 8;
        ((uint4*)g_Bhi)[dst] = make_uint4(h0.x, h0.y, h1.x, h1.y);
        ((uint4*)g_Blo)[dst] = make_uint4(l0.x, l0.y, l1.x, l1.y);
    }
}

// ===========================================================================
// c = sigmoid(-gate), v = sigmoid(gate)*g(hidden)
// ===========================================================================
__device__ __forceinline__ void compute_cv(float hidden, float gate,
                                           float& c, float& v)
{
    const float eg = __expf(gate);
    c = 1.f / (1.f + eg);
    const float z = 1.f - c;
    float gg;
    if (hidden >= 0.f) gg = hidden + 0.5f;
    else               gg = 1.f / (1.f + __expf(-hidden));
    v = z * gg;
}

// ===========================================================================
// GEMM: hg = [Ahi|Ahi|Alo] * [Bhi|Blo|Bhi]^T over virtual K = 3072 bf16.
// CTA 128x128, BK=64, 3-stage cp.async, ldmatrix, 8 warps, 2 CTAs/SM.
// Epilogue: compute (c,v), write g_cv, AND compose per-16-step chunk
// transforms in smem (fused scan_passA).
// ===========================================================================
#define TM 128
#define TN 128
#define BKB 64
#define KCHUNKS 48                 // 3 segments x 16 chunks
#define AST 16384
#define STAGE_B 32768
#define GEMM_SMEM (3 * STAGE_B)    // 98304

// Epilogue smem layout (aliases pipeline stages): per channel column of
// 128 rows x (c,v) float2, pitch 258 floats (1032 B) for bank spread.
#define CH_PITCH 258               // floats per channel column
// 64 * 258 * 4 = 66048 bytes <= 98304 OK

#define CP_ASYNC16(dst, src) \
    asm volatile("cp.async.cg.shared.global [%0], [%1], 16;" \
                 :: "r"(dst), "l"(src))
#define CP_COMMIT() asm volatile("cp.async.commit_group;")
#define CP_WAIT1()  asm volatile("cp.async.wait_group 1;")
#define CP_WAIT0()  asm volatile("cp.async.wait_group 0;")
#define LDSM4(r0, r1, r2, r3, addr) \
    asm volatile("ldmatrix.sync.aligned.m8n8.x4.shared.b16 {%0,%1,%2,%3}, [%4];" \
                 : "=r"(r0), "=r"(r1), "=r"(r2), "=r"(r3) : "r"(addr))

__device__ __forceinline__ uint32_t smem_u32(const void* p) {
    uint32_t a;
    asm("{ .reg .u64 t; cvta.to.shared.u64 t, %1; cvt.u32.u64 %0, t; }"
        : "=r"(a) : "l"(p));
    return a;
}

__device__ __forceinline__ void mma_bf16(float& d0, float& d1, float& d2, float& d3,
                                         uint32_t a0, uint32_t a1, uint32_t a2, uint32_t a3,
                                         uint32_t b0, uint32_t b1)
{
    asm volatile(
        "mma.sync.aligned.m16n8k16.row.col.f32.bf16.bf16.f32 "
        "{%0,%1,%2,%3}, {%4,%5,%6,%7}, {%8,%9}, {%0,%1,%2,%3};"
        : "+f"(d0), "+f"(d1), "+f"(d2), "+f"(d3)
        : "r"(a0), "r"(a1), "r"(a2), "r"(a3), "r"(b0), "r"(b1));
}

struct ChunkSrc {
    const __nv_bfloat16* a;
    const __nv_bfloat16* b;
    int kk;
};
__device__ __forceinline__ ChunkSrc chunk_src(int kc) {
    ChunkSrc s;
    const int seg = kc >> 4;
    s.kk = (kc & 15) * BKB;
    s.a = (seg < 2) ? g_Ahi : g_Alo;
    s.b = (seg == 1) ? g_Blo : g_Bhi;
    return s;
}

__global__ __launch_bounds__(256, 2)
void mingru_gemm()
{
    extern __shared__ char smem[];
    const uint32_t sb = smem_u32(smem);
    const int tid = threadIdx.x;
    const int wid = tid >> 5, lid = tid & 31;
    const int m0 = blockIdx.y * TM, n0 = blockIdx.x * TN;

    const int crow0 = tid >> 3;
    const int cuc   = tid & 7;
    const uint32_t cdst0 = (uint32_t)(crow0 * 128 + ((cuc * 16) ^ ((crow0 & 7) << 4)));

    const int rr = lid & 7, q = lid >> 3;
    const int arow = (q & 1) * 8 + rr;
    const uint32_t acb = (uint32_t)((q >> 1) * 16);
    const int brow = (q >> 1) * 8 + rr;
    const uint32_t bcb = (uint32_t)((q & 1) * 16);
    const uint32_t lxr = (uint32_t)(rr << 4);

    const int wm = (wid >> 2) * 64;
    const int wn = (wid & 3) * 32;
    const int gg = lid >> 2;
    const int t4 = lid & 3;

    float acc[4][4][4];
#pragma unroll
    for (int i = 0; i < 4; i++)
#pragma unroll
        for (int j = 0; j < 4; j++)
#pragma unroll
            for (int e = 0; e < 4; e++) acc[i][j][e] = 0.f;

    auto issue = [&](int kc, int s) {
        const ChunkSrc cs = chunk_src(kc);
        const uint32_t As = sb + s * STAGE_B;
        const uint32_t Bs = As + AST;
#pragma unroll
        for (int i = 0; i < 4; i++) {
            const int row = crow0 + i * 32;
            const uint32_t d = cdst0 + i * 4096;
            CP_ASYNC16(As + d, cs.a + (size_t)(m0 + row) * KK + cs.kk + cuc * 8);
            CP_ASYNC16(Bs + d, cs.b + (size_t)(n0 + row) * KK + cs.kk + cuc * 8);
        }
        CP_COMMIT();
    };

    issue(0, 0);
    issue(1, 1);

    for (int kc = 0; kc < KCHUNKS; kc++) {
        if (kc == KCHUNKS - 1) { CP_WAIT0(); } else { CP_WAIT1(); }
        __syncthreads();

        if (kc + 2 < KCHUNKS) issue(kc + 2, (kc + 2) % 3);

        const uint32_t As = sb + (kc % 3) * STAGE_B;
        const uint32_t Bs = As + AST;

#pragma unroll
        for (int kt = 0; kt < 4; kt++) {
            uint32_t af[4][4];
#pragma unroll
            for (int i = 0; i < 4; i++) {
                const uint32_t addr = As + (uint32_t)((wm + i * 16 + arow) * 128)
                                    + (((uint32_t)(kt * 32) + acb) ^ lxr);
                LDSM4(af[i][0], af[i][1], af[i][2], af[i][3], addr);
            }
            uint32_t bf[4][2];
            {
                const uint32_t addr0 = Bs + (uint32_t)((wn + brow) * 128)
                                     + (((uint32_t)(kt * 32) + bcb) ^ lxr);
                LDSM4(bf[0][0], bf[0][1], bf[1][0], bf[1][1], addr0);
                LDSM4(bf[2][0], bf[2][1], bf[3][0], bf[3][1], addr0 + 16 * 128);
            }
#pragma unroll
            for (int i = 0; i < 4; i++)
#pragma unroll
                for (int j = 0; j < 4; j++)
                    mma_bf16(acc[i][j][0], acc[i][j][1], acc[i][j][2], acc[i][j][3],
                             af[i][0], af[i][1], af[i][2], af[i][3],
                             bf[j][0], bf[j][1]);
        }
    }

    // Make sure all warps are done reading pipeline smem before aliasing it.
    __syncthreads();
    float* scv = (float*)smem;   // [64 channels][CH_PITCH floats]

    // Epilogue: (c,v) per accumulator pair -> global g_cv + smem tile.
    // acc[i][j] = one channel (ch_local), rows wm+i*16+gg and +8.
#pragma unroll
    for (int i = 0; i < 4; i++) {
        const int rl0 = wm + i * 16 + gg;          // local row (timestep in tile)
        const int r0 = m0 + rl0;
#pragma unroll
        for (int j = 0; j < 4; j++) {
            const int c = wn + j * 8 + t4 * 2;     // local g_cv col (even)
            const int ch_local = c >> 1;           // 0..63
            float cv0, vv0, cv1, vv1;
            compute_cv(acc[i][j][0], acc[i][j][1], cv0, vv0);
            compute_cv(acc[i][j][2], acc[i][j][3], cv1, vv1);
            *(float2*)(g_cv + (size_t)r0 * NN + n0 + c)       = make_float2(cv0, vv0);
            *(float2*)(g_cv + (size_t)(r0 + 8) * NN + n0 + c) = make_float2(cv1, vv1);
            *(float2*)&scv[ch_local * CH_PITCH + rl0 * 2]       = make_float2(cv0, vv0);
            *(float2*)&scv[ch_local * CH_PITCH + (rl0 + 8) * 2] = make_float2(cv1, vv1);
        }
    }
    __syncthreads();

    // Fused scan_passA: compose 8 sub-chunks of 16 timesteps x 64 channels.
    // Thread: sc = tid>>5 (sub-chunk), l = tid&31 -> channels 2l, 2l+1.
    {
        const int sc = tid >> 5;
        const int l  = tid & 31;
        const int ch0 = 2 * l;
        float C0 = 1.f, V0 = 0.f, C1 = 1.f, V1 = 0.f;
        const float* p0 = &scv[ch0 * CH_PITCH + sc * 32];
        const float* p1 = p0 + CH_PITCH;
#pragma unroll
        for (int r = 0; r < 16; r++) {
            const float c0 = p0[r * 2], v0 = p0[r * 2 + 1];
            const float c1 = p1[r * 2], v1 = p1[r * 2 + 1];
            V0 = fmaf(c0, V0, v0);  C0 *= c0;
            V1 = fmaf(c1, V1, v1);  C1 *= c1;
        }
        const int b = blockIdx.y >> 5;                      // batch
        const int k = ((blockIdx.y & 31) << 3) + sc;        // global chunk 0..255
        const int chg = b * DD + (n0 >> 1) + ch0;           // global channel
        *(float2*)&g_chunkC[k * NCH + chg] = make_float2(C0, C1);
        *(float2*)&g_chunkV[k * NCH + chg] = make_float2(V0, V1);
    }
}

// ===========================================================================
// passB: warp-per-channel associative scan over the 256 chunk transforms.
// ===========================================================================
#define KPL (NCHUNK / 32)   // 8 chunks per lane
__global__ __launch_bounds__(256)
void scan_passB()
{
    const int warp = (blockIdx.x * 256 + threadIdx.x) >> 5;  // 0..4095 == ch
    const int lane = threadIdx.x & 31;
    const int ch = warp;

    float c8[KPL], v8[KPL];
#pragma unroll
    for (int j = 0; j < KPL; j++) {
        const int k = lane * KPL + j;
        c8[j] = g_chunkC[k * NCH + ch];
        v8[j] = g_chunkV[k * NCH + ch];
    }
    float C = c8[0], V = v8[0];
#pragma unroll
    for (int j = 1; j < KPL; j++) {
        V = fmaf(c8[j], V, v8[j]);
        C *= c8[j];
    }
#pragma unroll
    for (int off = 1; off < 32; off <<= 1) {
        const float Cp = __shfl_up_sync(0xFFFFFFFFu, C, off);
        const float Vp = __shfl_up_sync(0xFFFFFFFFu, V, off);
        if (lane >= off) {
            V = fmaf(C, Vp, V);
            C *= Cp;
        }
    }
    const float Vprev = __shfl_up_sync(0xFFFFFFFFu, V, 1);
    float h = (lane == 0) ? 0.f : Vprev;
#pragma unroll
    for (int j = 0; j < KPL; j++) {
        const int k = lane * KPL + j;
        g_h0[k * NCH + ch] = h;
        h = fmaf(c8[j], h, v8[j]);
    }
}

// ===========================================================================
// passC: replay within chunk from h0, write output.
// ===========================================================================
__global__ __launch_bounds__(256)
void scan_passC(float* __restrict__ out)
{
    const int t = threadIdx.x;
    const int k = blockIdx.x;
    const int b = blockIdx.y;
    const size_t base = ((size_t)b * SS + (size_t)k * CLEN) * NN + t * 8;
    const float4* p0 = (const float4*)(g_cv + base);

    const int ch = b * DD + t * 4;
    const float4 h0v = *(const float4*)&g_h0[k * NCH + ch];
    float h[4] = {h0v.x, h0v.y, h0v.z, h0v.w};

    float4* po = (float4*)(out + ((size_t)b * SS + (size_t)k * CLEN) * DD + t * 4);
#pragma unroll 8
    for (int s = 0; s < CLEN; s++) {
        const float4 a = p0[s * (NN / 4)];
        const float4 bq = p0[s * (NN / 4) + 1];
        h[0] = fmaf(a.x, h[0], a.y);
        h[1] = fmaf(a.z, h[1], a.w);
        h[2] = fmaf(bq.x, h[2], bq.y);
        h[3] = fmaf(bq.z, h[3], bq.w);
        po[s * (DD / 4)] = make_float4(h[0], h[1], h[2], h[3]);
    }
}

// ===========================================================================
extern "C" void kernel_launch(void* const* d_in, const int* in_sizes, int n_in,
                              void* d_out, int out_size)
{
    const float* x = (const float*)d_in[0];   // [B, S, D]
    const float* W = (const float*)d_in[1];   // [2D, D]
    float* out = (float*)d_out;

    cudaFuncSetAttribute(mingru_gemm,
                         cudaFuncAttributeMaxDynamicSharedMemorySize, GEMM_SMEM);

    convert_kernel<<<(unsigned)((A8 + B8 + 255) / 256), 256>>>(x, W);

    dim3 ggrid(NN / TN, MM / TM);            // (16, 128)
    mingru_gemm<<<ggrid, 256, GEMM_SMEM>>>();

    scan_passB<<<(NCH * 32) / 256, 256>>>();

    dim3 sgrid(NCHUNK, BB);                  // (256, 4)
    scan_passC<<<sgrid, 256>>>(out);
}